// round 14
// baseline (speedup 1.0000x reference)
#include <cuda_runtime.h>
#include <cstdint>

// Problem constants
#define BB 2
#define SS 2048
#define HH 1024
#define NHEAD 16
#define HD 64
#define H3 (3*HH)
#define NTOK (BB*SS)          // 4096
#define EPSF 1e-5f

// Scratch (device globals — no allocations allowed)
__device__ float g_qkv[(size_t)NTOK * H3];   // [4096, 3072]
__device__ float g_att[(size_t)NTOK * HH];   // [4096, 1024] (tf32-rounded)
__device__ float g_hid[(size_t)NTOK * HH];   // tf32-rounded hidden
__device__ float g_wa[(size_t)HH * H3];      // tf32-rounded W_attn
__device__ float g_wp[(size_t)HH * HH];      // tf32-rounded W_proj

// ---------------------------------------------------------------------------
// tf32 helpers
// ---------------------------------------------------------------------------
__device__ __forceinline__ unsigned f2tf(float f) {
    unsigned u;
    asm("cvt.rna.tf32.f32 %0, %1;" : "=r"(u) : "f"(f));
    return u;
}

__device__ __forceinline__ void mma_tf32(float* c,
    unsigned a0, unsigned a1, unsigned a2, unsigned a3,
    unsigned b0, unsigned b1)
{
    asm volatile(
        "mma.sync.aligned.m16n8k8.row.col.f32.tf32.tf32.f32 "
        "{%0,%1,%2,%3}, {%4,%5,%6,%7}, {%8,%9}, {%0,%1,%2,%3};"
        : "+f"(c[0]), "+f"(c[1]), "+f"(c[2]), "+f"(c[3])
        : "r"(a0), "r"(a1), "r"(a2), "r"(a3), "r"(b0), "r"(b1));
}

__device__ __forceinline__ void cp16(void* smem_dst, const void* gsrc) {
    unsigned d = (unsigned)__cvta_generic_to_shared(smem_dst);
    asm volatile("cp.async.cg.shared.global [%0], [%1], 16;\n"
                 :: "r"(d), "l"(gsrc));
}
__device__ __forceinline__ void cp_commit() {
    asm volatile("cp.async.commit_group;\n");
}
__device__ __forceinline__ void cp_wait1() {
    asm volatile("cp.async.wait_group 1;\n");
}

// ---------------------------------------------------------------------------
// Pre-round fp32 -> tf32(rna) bits, stored as fp32.
// ---------------------------------------------------------------------------
__global__ __launch_bounds__(256)
void round_tf32_kernel(const float* __restrict__ in, float* __restrict__ out)
{
    int i = (blockIdx.x * 256 + threadIdx.x) * 4;
    float4 v = *(const float4*)(in + i);
    v.x = __uint_as_float(f2tf(v.x));
    v.y = __uint_as_float(f2tf(v.y));
    v.z = __uint_as_float(f2tf(v.z));
    v.w = __uint_as_float(f2tf(v.w));
    *(float4*)(out + i) = v;
}

// ---------------------------------------------------------------------------
// tf32 tensor-core GEMM (verified R9 version):  C = A @ B + bias
// Block tile 128x128, 8 warps (2x4), warp tile 64x32, BK=16,
// 3-stage cp.async pipeline, static smem (A pitch 20, B pitch 136).
// Inputs must be tf32-pre-rounded.
// ---------------------------------------------------------------------------
#define STAGES 3

__global__ __launch_bounds__(256, 2)
void gemm_tf32(const float* __restrict__ A, const float* __restrict__ B,
               const float* __restrict__ bias, float* __restrict__ C,
               int M, int N, int K)
{
    __shared__ float sA[STAGES][128][20];
    __shared__ float sB[STAGES][16][136];

    const int tid  = threadIdx.x;
    const int warp = tid >> 5;
    const int lane = tid & 31;
    const int g    = lane >> 2;
    const int tig  = lane & 3;
    const int wm   = (warp >> 2) * 64;
    const int wn   = (warp & 3) * 32;
    const int bm   = blockIdx.y * 128;
    const int bn   = blockIdx.x * 128;

    const int a_r = tid >> 2;
    const int a_c = (tid & 3) * 4;
    const int b_r = tid >> 5;
    const int b_c = (tid & 31) * 4;

    const float* aptr0 = &A[(size_t)(bm + a_r) * K + a_c];
    const float* aptr1 = &A[(size_t)(bm + a_r + 64) * K + a_c];
    const float* bptr0 = &B[(size_t)b_r * N + bn + b_c];
    const float* bptr1 = &B[(size_t)(b_r + 8) * N + bn + b_c];

    float acc[4][4][4];
    #pragma unroll
    for (int i = 0; i < 4; ++i)
        #pragma unroll
        for (int j = 0; j < 4; ++j)
            #pragma unroll
            for (int e = 0; e < 4; ++e) acc[i][j][e] = 0.f;

    const int nkt = K >> 4;

    #pragma unroll
    for (int s = 0; s < STAGES - 1; ++s) {
        int k0 = s * 16;
        cp16(&sA[s][a_r][a_c],      aptr0 + k0);
        cp16(&sA[s][a_r + 64][a_c], aptr1 + k0);
        cp16(&sB[s][b_r][b_c],      bptr0 + (size_t)k0 * N);
        cp16(&sB[s][b_r + 8][b_c],  bptr1 + (size_t)k0 * N);
        cp_commit();
    }

    for (int kt = 0; kt < nkt; ++kt) {
        cp_wait1();
        __syncthreads();

        int pf = kt + STAGES - 1;
        if (pf < nkt) {
            int s = pf % STAGES;
            int k0 = pf * 16;
            cp16(&sA[s][a_r][a_c],      aptr0 + k0);
            cp16(&sA[s][a_r + 64][a_c], aptr1 + k0);
            cp16(&sB[s][b_r][b_c],      bptr0 + (size_t)k0 * N);
            cp16(&sB[s][b_r + 8][b_c],  bptr1 + (size_t)k0 * N);
        }
        cp_commit();

        const int s = kt % STAGES;
        #pragma unroll
        for (int kk = 0; kk < 16; kk += 8) {
            unsigned af[4][4], bf[4][2];
            #pragma unroll
            for (int i = 0; i < 4; ++i) {
                int m = wm + 16 * i + g;
                af[i][0] = __float_as_uint(sA[s][m    ][kk + tig]);
                af[i][1] = __float_as_uint(sA[s][m + 8][kk + tig]);
                af[i][2] = __float_as_uint(sA[s][m    ][kk + tig + 4]);
                af[i][3] = __float_as_uint(sA[s][m + 8][kk + tig + 4]);
            }
            #pragma unroll
            for (int j = 0; j < 4; ++j) {
                int n = wn + 8 * j + g;
                bf[j][0] = __float_as_uint(sB[s][kk + tig    ][n]);
                bf[j][1] = __float_as_uint(sB[s][kk + tig + 4][n]);
            }
            #pragma unroll
            for (int i = 0; i < 4; ++i)
                #pragma unroll
                for (int j = 0; j < 4; ++j)
                    mma_tf32(acc[i][j], af[i][0], af[i][1], af[i][2], af[i][3],
                             bf[j][0], bf[j][1]);
        }
    }

    #pragma unroll
    for (int i = 0; i < 4; ++i) {
        #pragma unroll
        for (int j = 0; j < 4; ++j) {
            int gm = bm + wm + 16 * i + g;
            int gn = bn + wn + 8 * j + 2 * tig;
            float bx = bias[gn], by = bias[gn + 1];
            float2 r0 = make_float2(acc[i][j][0] + bx, acc[i][j][1] + by);
            float2 r1 = make_float2(acc[i][j][2] + bx, acc[i][j][3] + by);
            *(float2*)&C[(size_t)gm * N + gn] = r0;
            *(float2*)&C[(size_t)(gm + 8) * N + gn] = r1;
        }
    }
}

// ---------------------------------------------------------------------------
// QK LayerNorm over head_dim=64, in place. One warp per (tensor,tok,head) row.
// Softmax scale (HD^-0.5 = 0.125) folded into q.
// ---------------------------------------------------------------------------
__global__ __launch_bounds__(256)
void qk_ln_kernel(float* __restrict__ qkv,
                  const float* __restrict__ qg, const float* __restrict__ qb,
                  const float* __restrict__ kg, const float* __restrict__ kb)
{
    int warp = (blockIdx.x * blockDim.x + threadIdx.x) >> 5;
    int lane = threadIdx.x & 31;
    int is_k = (warp >= NTOK * NHEAD) ? 1 : 0;
    int r = warp - is_k * NTOK * NHEAD;
    int tok = r >> 4;
    int hd = r & 15;

    float* base = qkv + (size_t)tok * H3 + is_k * HH + hd * HD;
    float2 v = *reinterpret_cast<float2*>(&base[lane * 2]);

    float s = v.x + v.y;
    #pragma unroll
    for (int m = 16; m; m >>= 1) s += __shfl_xor_sync(0xffffffffu, s, m);
    float mu = s * (1.f / 64.f);

    float dx = v.x - mu, dy = v.y - mu;
    float vs = dx * dx + dy * dy;
    #pragma unroll
    for (int m = 16; m; m >>= 1) vs += __shfl_xor_sync(0xffffffffu, vs, m);
    float rstd = rsqrtf(vs * (1.f / 64.f) + EPSF);

    const float* gm = is_k ? kg : qg;
    const float* be = is_k ? kb : qb;
    float scale = is_k ? 1.f : 0.125f;

    float2 o;
    o.x = (dx * rstd * gm[lane * 2 + 0] + be[lane * 2 + 0]) * scale;
    o.y = (dy * rstd * gm[lane * 2 + 1] + be[lane * 2 + 1]) * scale;
    *reinterpret_cast<float2*>(&base[lane * 2]) = o;
}

// ---------------------------------------------------------------------------
// Causal attention v2: Br=128 query rows/block, 8 warps (256 threads),
// Bc=64 k-tiles, FA2 online softmax, tf32 MMA. Warp w owns rows
// [q0+16w, q0+16w+16) with the same fragment pattern as v1 (bit-identical
// arithmetic per row). K/V loaded once per 128 query rows (half the traffic).
// ---------------------------------------------------------------------------
#define QLD 68
#define VLD 72
// Q:128x68, P:128x68, K:64x68, V:64x72 floats
#define ATT_SMEM ((128 * QLD + 128 * QLD + 64 * QLD + 64 * VLD) * 4)  // 105472

__global__ __launch_bounds__(256, 2)
void attn_tf32(const float* __restrict__ qkv, float* __restrict__ out)
{
    extern __shared__ unsigned sm[];
    unsigned* q_sm = sm;                       // 128 x QLD
    unsigned* p_sm = sm + 128 * QLD;           // 128 x QLD
    unsigned* k_sm = sm + 2 * 128 * QLD;       // 64 x QLD
    unsigned* v_sm = sm + 2 * 128 * QLD + 64 * QLD;   // 64 x VLD

    const int tid  = threadIdx.x;
    const int warp = tid >> 5;
    const int lane = tid & 31;
    const int g    = lane >> 2;
    const int tig  = lane & 3;
    const int wr   = warp * 16;
    const int bh = blockIdx.y;
    const int b = bh >> 4;
    const int h = bh & 15;
    const int q0 = blockIdx.x * 128;
    const size_t tok0 = (size_t)b * SS;

    // Load Q tile (128 x 64) with tf32 rounding
    #pragma unroll
    for (int it = 0; it < 8; ++it) {
        int i = tid + it * 256;
        int r = i >> 4, c = (i & 15) * 4;
        float4 v4 = *(const float4*)&qkv[(tok0 + q0 + r) * H3 + h * HD + c];
        q_sm[r * QLD + c + 0] = f2tf(v4.x);
        q_sm[r * QLD + c + 1] = f2tf(v4.y);
        q_sm[r * QLD + c + 2] = f2tf(v4.z);
        q_sm[r * QLD + c + 3] = f2tf(v4.w);
    }

    float m0 = -1e30f, m1 = -1e30f, l0 = 0.f, l1 = 0.f;
    float o[8][4];
    #pragma unroll
    for (int j = 0; j < 8; ++j)
        #pragma unroll
        for (int e = 0; e < 4; ++e) o[j][e] = 0.f;
    __syncthreads();

    const int ntiles = 2 * blockIdx.x + 2;   // causal: k0c <= q0 + 127
    for (int t = 0; t < ntiles; ++t) {
        const int k0c = t * 64;
        // Load K and V tiles (64 x 64 each)
        #pragma unroll
        for (int it = 0; it < 4; ++it) {
            int i = tid + it * 256;
            int r = i >> 4, c = (i & 15) * 4;
            size_t base = (tok0 + k0c + r) * H3 + h * HD + c;
            float4 kv = *(const float4*)&qkv[base + HH];
            float4 vv = *(const float4*)&qkv[base + 2 * HH];
            k_sm[r * QLD + c + 0] = f2tf(kv.x);
            k_sm[r * QLD + c + 1] = f2tf(kv.y);
            k_sm[r * QLD + c + 2] = f2tf(kv.z);
            k_sm[r * QLD + c + 3] = f2tf(kv.w);
            v_sm[r * VLD + c + 0] = f2tf(vv.x);
            v_sm[r * VLD + c + 1] = f2tf(vv.y);
            v_sm[r * VLD + c + 2] = f2tf(vv.z);
            v_sm[r * VLD + c + 3] = f2tf(vv.w);
        }
        __syncthreads();

        // S = Q @ K^T  (scale folded into Q)
        float s[8][4];
        #pragma unroll
        for (int j = 0; j < 8; ++j)
            #pragma unroll
            for (int e = 0; e < 4; ++e) s[j][e] = 0.f;

        #pragma unroll
        for (int ks = 0; ks < 8; ++ks) {
            unsigned a0 = q_sm[(wr + g    ) * QLD + 8 * ks + tig];
            unsigned a1 = q_sm[(wr + g + 8) * QLD + 8 * ks + tig];
            unsigned a2 = q_sm[(wr + g    ) * QLD + 8 * ks + tig + 4];
            unsigned a3 = q_sm[(wr + g + 8) * QLD + 8 * ks + tig + 4];
            #pragma unroll
            for (int j = 0; j < 8; ++j) {
                unsigned b0 = k_sm[(8 * j + g) * QLD + 8 * ks + tig];
                unsigned b1 = k_sm[(8 * j + g) * QLD + 8 * ks + tig + 4];
                mma_tf32(s[j], a0, a1, a2, a3, b0, b1);
            }
        }

        // Causal mask: needed when this k-tile reaches past this warp's rows
        if (k0c + 63 > q0 + wr) {
            int rg0 = q0 + wr + g;
            int rg1 = rg0 + 8;
            #pragma unroll
            for (int j = 0; j < 8; ++j) {
                int cg = k0c + 8 * j + 2 * tig;
                if (cg     > rg0) s[j][0] = -1e30f;
                if (cg + 1 > rg0) s[j][1] = -1e30f;
                if (cg     > rg1) s[j][2] = -1e30f;
                if (cg + 1 > rg1) s[j][3] = -1e30f;
            }
        }

        // Online softmax (rows g and g+8 within warp tile; quad reduce)
        float rmax0 = -1e30f, rmax1 = -1e30f;
        #pragma unroll
        for (int j = 0; j < 8; ++j) {
            rmax0 = fmaxf(rmax0, fmaxf(s[j][0], s[j][1]));
            rmax1 = fmaxf(rmax1, fmaxf(s[j][2], s[j][3]));
        }
        rmax0 = fmaxf(rmax0, __shfl_xor_sync(0xffffffffu, rmax0, 1));
        rmax0 = fmaxf(rmax0, __shfl_xor_sync(0xffffffffu, rmax0, 2));
        rmax1 = fmaxf(rmax1, __shfl_xor_sync(0xffffffffu, rmax1, 1));
        rmax1 = fmaxf(rmax1, __shfl_xor_sync(0xffffffffu, rmax1, 2));

        float mn0 = fmaxf(m0, rmax0);
        float mn1 = fmaxf(m1, rmax1);
        float sum0 = 0.f, sum1 = 0.f;
        #pragma unroll
        for (int j = 0; j < 8; ++j) {
            s[j][0] = __expf(s[j][0] - mn0); sum0 += s[j][0];
            s[j][1] = __expf(s[j][1] - mn0); sum0 += s[j][1];
            s[j][2] = __expf(s[j][2] - mn1); sum1 += s[j][2];
            s[j][3] = __expf(s[j][3] - mn1); sum1 += s[j][3];
        }
        sum0 += __shfl_xor_sync(0xffffffffu, sum0, 1);
        sum0 += __shfl_xor_sync(0xffffffffu, sum0, 2);
        sum1 += __shfl_xor_sync(0xffffffffu, sum1, 1);
        sum1 += __shfl_xor_sync(0xffffffffu, sum1, 2);

        float al0 = __expf(m0 - mn0);
        float al1 = __expf(m1 - mn1);
        l0 = l0 * al0 + sum0;
        l1 = l1 * al1 + sum1;
        m0 = mn0; m1 = mn1;

        #pragma unroll
        for (int j = 0; j < 8; ++j) {
            o[j][0] *= al0; o[j][1] *= al0;
            o[j][2] *= al1; o[j][3] *= al1;
            p_sm[(wr + g    ) * QLD + 8 * j + 2 * tig    ] = f2tf(s[j][0]);
            p_sm[(wr + g    ) * QLD + 8 * j + 2 * tig + 1] = f2tf(s[j][1]);
            p_sm[(wr + g + 8) * QLD + 8 * j + 2 * tig    ] = f2tf(s[j][2]);
            p_sm[(wr + g + 8) * QLD + 8 * j + 2 * tig + 1] = f2tf(s[j][3]);
        }
        __syncwarp();

        // O += P @ V
        #pragma unroll
        for (int ks = 0; ks < 8; ++ks) {
            unsigned a0 = p_sm[(wr + g    ) * QLD + 8 * ks + tig];
            unsigned a1 = p_sm[(wr + g + 8) * QLD + 8 * ks + tig];
            unsigned a2 = p_sm[(wr + g    ) * QLD + 8 * ks + tig + 4];
            unsigned a3 = p_sm[(wr + g + 8) * QLD + 8 * ks + tig + 4];
            #pragma unroll
            for (int j = 0; j < 8; ++j) {
                unsigned b0 = v_sm[(8 * ks + tig    ) * VLD + 8 * j + g];
                unsigned b1 = v_sm[(8 * ks + tig + 4) * VLD + 8 * j + g];
                mma_tf32(o[j], a0, a1, a2, a3, b0, b1);
            }
        }
        __syncthreads();
    }

    // Normalize, tf32-round, write out (feeds proj GEMM as pre-rounded A)
    float i0 = 1.f / l0, i1 = 1.f / l1;
    #pragma unroll
    for (int j = 0; j < 8; ++j) {
        int gn = h * HD + 8 * j + 2 * tig;
        float2 r0 = make_float2(__uint_as_float(f2tf(o[j][0] * i0)),
                                __uint_as_float(f2tf(o[j][1] * i0)));
        float2 r1 = make_float2(__uint_as_float(f2tf(o[j][2] * i1)),
                                __uint_as_float(f2tf(o[j][3] * i1)));
        *(float2*)&out[(tok0 + q0 + wr + g    ) * HH + gn] = r0;
        *(float2*)&out[(tok0 + q0 + wr + g + 8) * HH + gn] = r1;
    }
}

// ---------------------------------------------------------------------------
extern "C" void kernel_launch(void* const* d_in, const int* in_sizes, int n_in,
                              void* d_out, int out_size)
{
    const float* hidden = (const float*)d_in[0];
    const float* W_attn = (const float*)d_in[1];
    const float* b_attn = (const float*)d_in[2];
    const float* W_proj = (const float*)d_in[3];
    const float* b_proj = (const float*)d_in[4];
    const float* q_gamma = (const float*)d_in[5];
    const float* q_beta  = (const float*)d_in[6];
    const float* k_gamma = (const float*)d_in[7];
    const float* k_beta  = (const float*)d_in[8];
    float* out = (float*)d_out;

    float* qkv; cudaGetSymbolAddress((void**)&qkv, g_qkv);
    float* att; cudaGetSymbolAddress((void**)&att, g_att);
    float* hid; cudaGetSymbolAddress((void**)&hid, g_hid);
    float* wa;  cudaGetSymbolAddress((void**)&wa,  g_wa);
    float* wp;  cudaGetSymbolAddress((void**)&wp,  g_wp);

    static bool attr_set = false;
    if (!attr_set) {
        cudaFuncSetAttribute(attn_tf32,
                             cudaFuncAttributeMaxDynamicSharedMemorySize, ATT_SMEM);
        attr_set = true;
    }

    // 0) Pre-round GEMM inputs to tf32 (rna) once
    round_tf32_kernel<<<(NTOK * HH) / 1024, 256>>>(hidden, hid);
    round_tf32_kernel<<<(HH * H3) / 1024, 256>>>(W_attn, wa);
    round_tf32_kernel<<<(HH * HH) / 1024, 256>>>(W_proj, wp);

    // 1) QKV GEMM: [4096,1024] @ [1024,3072] + bias
    gemm_tf32<<<dim3(H3 / 128, NTOK / 128), 256>>>(
        hid, wa, b_attn, qkv, NTOK, H3, HH);

    // 2) QK LayerNorm in place (softmax scale folded into q)
    qk_ln_kernel<<<(2 * NTOK * NHEAD) / 8, 256>>>(
        qkv, q_gamma, q_beta, k_gamma, k_beta);

    // 3) Causal attention v2 (Br=128, 8 warps, tf32 MMA)
    attn_tf32<<<dim3(SS / 128, BB * NHEAD), 256, ATT_SMEM>>>(qkv, att);

    // 4) Output projection: [4096,1024] @ [1024,1024] + bias
    gemm_tf32<<<dim3(HH / 128, NTOK / 128), 256>>>(
        att, wp, b_proj, out, NTOK, HH, HH);
}

// round 17
// speedup vs baseline: 1.0547x; 1.0547x over previous
#include <cuda_runtime.h>
#include <cstdint>

// Problem constants
#define BB 2
#define SS 2048
#define HH 1024
#define NHEAD 16
#define HD 64
#define H3 (3*HH)
#define NTOK (BB*SS)          // 4096
#define EPSF 1e-5f

// Scratch (device globals — no allocations allowed)
__device__ float g_qkv[(size_t)NTOK * H3];   // [4096, 3072]
__device__ float g_att[(size_t)NTOK * HH];   // [4096, 1024] (tf32-rounded)
__device__ float g_hid[(size_t)NTOK * HH];   // tf32-rounded hidden
__device__ float g_wa[(size_t)HH * H3];      // tf32-rounded W_attn
__device__ float g_wp[(size_t)HH * HH];      // tf32-rounded W_proj

// ---------------------------------------------------------------------------
// tf32 helpers
// ---------------------------------------------------------------------------
__device__ __forceinline__ unsigned f2tf(float f) {
    unsigned u;
    asm("cvt.rna.tf32.f32 %0, %1;" : "=r"(u) : "f"(f));
    return u;
}

__device__ __forceinline__ void mma_tf32(float* c,
    unsigned a0, unsigned a1, unsigned a2, unsigned a3,
    unsigned b0, unsigned b1)
{
    asm volatile(
        "mma.sync.aligned.m16n8k8.row.col.f32.tf32.tf32.f32 "
        "{%0,%1,%2,%3}, {%4,%5,%6,%7}, {%8,%9}, {%0,%1,%2,%3};"
        : "+f"(c[0]), "+f"(c[1]), "+f"(c[2]), "+f"(c[3])
        : "r"(a0), "r"(a1), "r"(a2), "r"(a3), "r"(b0), "r"(b1));
}

__device__ __forceinline__ void cp16(void* smem_dst, const void* gsrc) {
    unsigned d = (unsigned)__cvta_generic_to_shared(smem_dst);
    asm volatile("cp.async.cg.shared.global [%0], [%1], 16;\n"
                 :: "r"(d), "l"(gsrc));
}
__device__ __forceinline__ void cp_commit() {
    asm volatile("cp.async.commit_group;\n");
}
__device__ __forceinline__ void cp_wait1() {
    asm volatile("cp.async.wait_group 1;\n");
}

// ---------------------------------------------------------------------------
// Pre-round fp32 -> tf32(rna) bits, stored as fp32.
// ---------------------------------------------------------------------------
__global__ __launch_bounds__(256)
void round_tf32_kernel(const float* __restrict__ in, float* __restrict__ out)
{
    int i = (blockIdx.x * 256 + threadIdx.x) * 4;
    float4 v = *(const float4*)(in + i);
    v.x = __uint_as_float(f2tf(v.x));
    v.y = __uint_as_float(f2tf(v.y));
    v.z = __uint_as_float(f2tf(v.z));
    v.w = __uint_as_float(f2tf(v.w));
    *(float4*)(out + i) = v;
}

// ---------------------------------------------------------------------------
// tf32 tensor-core GEMM (verified R9 version):  C = A @ B + bias
// ---------------------------------------------------------------------------
#define STAGES 3

__global__ __launch_bounds__(256, 2)
void gemm_tf32(const float* __restrict__ A, const float* __restrict__ B,
               const float* __restrict__ bias, float* __restrict__ C,
               int M, int N, int K)
{
    __shared__ float sA[STAGES][128][20];
    __shared__ float sB[STAGES][16][136];

    const int tid  = threadIdx.x;
    const int warp = tid >> 5;
    const int lane = tid & 31;
    const int g    = lane >> 2;
    const int tig  = lane & 3;
    const int wm   = (warp >> 2) * 64;
    const int wn   = (warp & 3) * 32;
    const int bm   = blockIdx.y * 128;
    const int bn   = blockIdx.x * 128;

    const int a_r = tid >> 2;
    const int a_c = (tid & 3) * 4;
    const int b_r = tid >> 5;
    const int b_c = (tid & 31) * 4;

    const float* aptr0 = &A[(size_t)(bm + a_r) * K + a_c];
    const float* aptr1 = &A[(size_t)(bm + a_r + 64) * K + a_c];
    const float* bptr0 = &B[(size_t)b_r * N + bn + b_c];
    const float* bptr1 = &B[(size_t)(b_r + 8) * N + bn + b_c];

    float acc[4][4][4];
    #pragma unroll
    for (int i = 0; i < 4; ++i)
        #pragma unroll
        for (int j = 0; j < 4; ++j)
            #pragma unroll
            for (int e = 0; e < 4; ++e) acc[i][j][e] = 0.f;

    const int nkt = K >> 4;

    #pragma unroll
    for (int s = 0; s < STAGES - 1; ++s) {
        int k0 = s * 16;
        cp16(&sA[s][a_r][a_c],      aptr0 + k0);
        cp16(&sA[s][a_r + 64][a_c], aptr1 + k0);
        cp16(&sB[s][b_r][b_c],      bptr0 + (size_t)k0 * N);
        cp16(&sB[s][b_r + 8][b_c],  bptr1 + (size_t)k0 * N);
        cp_commit();
    }

    for (int kt = 0; kt < nkt; ++kt) {
        cp_wait1();
        __syncthreads();

        int pf = kt + STAGES - 1;
        if (pf < nkt) {
            int s = pf % STAGES;
            int k0 = pf * 16;
            cp16(&sA[s][a_r][a_c],      aptr0 + k0);
            cp16(&sA[s][a_r + 64][a_c], aptr1 + k0);
            cp16(&sB[s][b_r][b_c],      bptr0 + (size_t)k0 * N);
            cp16(&sB[s][b_r + 8][b_c],  bptr1 + (size_t)k0 * N);
        }
        cp_commit();

        const int s = kt % STAGES;
        #pragma unroll
        for (int kk = 0; kk < 16; kk += 8) {
            unsigned af[4][4], bf[4][2];
            #pragma unroll
            for (int i = 0; i < 4; ++i) {
                int m = wm + 16 * i + g;
                af[i][0] = __float_as_uint(sA[s][m    ][kk + tig]);
                af[i][1] = __float_as_uint(sA[s][m + 8][kk + tig]);
                af[i][2] = __float_as_uint(sA[s][m    ][kk + tig + 4]);
                af[i][3] = __float_as_uint(sA[s][m + 8][kk + tig + 4]);
            }
            #pragma unroll
            for (int j = 0; j < 4; ++j) {
                int n = wn + 8 * j + g;
                bf[j][0] = __float_as_uint(sB[s][kk + tig    ][n]);
                bf[j][1] = __float_as_uint(sB[s][kk + tig + 4][n]);
            }
            #pragma unroll
            for (int i = 0; i < 4; ++i)
                #pragma unroll
                for (int j = 0; j < 4; ++j)
                    mma_tf32(acc[i][j], af[i][0], af[i][1], af[i][2], af[i][3],
                             bf[j][0], bf[j][1]);
        }
    }

    #pragma unroll
    for (int i = 0; i < 4; ++i) {
        #pragma unroll
        for (int j = 0; j < 4; ++j) {
            int gm = bm + wm + 16 * i + g;
            int gn = bn + wn + 8 * j + 2 * tig;
            float bx = bias[gn], by = bias[gn + 1];
            float2 r0 = make_float2(acc[i][j][0] + bx, acc[i][j][1] + by);
            float2 r1 = make_float2(acc[i][j][2] + bx, acc[i][j][3] + by);
            *(float2*)&C[(size_t)gm * N + gn] = r0;
            *(float2*)&C[(size_t)(gm + 8) * N + gn] = r1;
        }
    }
}

// ---------------------------------------------------------------------------
// QK LayerNorm over head_dim=64, in place. One warp per (tensor,tok,head) row.
// ---------------------------------------------------------------------------
__global__ __launch_bounds__(256)
void qk_ln_kernel(float* __restrict__ qkv,
                  const float* __restrict__ qg, const float* __restrict__ qb,
                  const float* __restrict__ kg, const float* __restrict__ kb)
{
    int warp = (blockIdx.x * blockDim.x + threadIdx.x) >> 5;
    int lane = threadIdx.x & 31;
    int is_k = (warp >= NTOK * NHEAD) ? 1 : 0;
    int r = warp - is_k * NTOK * NHEAD;
    int tok = r >> 4;
    int hd = r & 15;

    float* base = qkv + (size_t)tok * H3 + is_k * HH + hd * HD;
    float2 v = *reinterpret_cast<float2*>(&base[lane * 2]);

    float s = v.x + v.y;
    #pragma unroll
    for (int m = 16; m; m >>= 1) s += __shfl_xor_sync(0xffffffffu, s, m);
    float mu = s * (1.f / 64.f);

    float dx = v.x - mu, dy = v.y - mu;
    float vs = dx * dx + dy * dy;
    #pragma unroll
    for (int m = 16; m; m >>= 1) vs += __shfl_xor_sync(0xffffffffu, vs, m);
    float rstd = rsqrtf(vs * (1.f / 64.f) + EPSF);

    const float* gm = is_k ? kg : qg;
    const float* be = is_k ? kb : qb;
    float scale = is_k ? 1.f : 0.125f;

    float2 o;
    o.x = (dx * rstd * gm[lane * 2 + 0] + be[lane * 2 + 0]) * scale;
    o.y = (dy * rstd * gm[lane * 2 + 1] + be[lane * 2 + 1]) * scale;
    *reinterpret_cast<float2*>(&base[lane * 2]) = o;
}

// ---------------------------------------------------------------------------
// Causal attention v3: Br=128 rows/block, 4 warps (128 threads); each warp
// owns 32 rows as TWO 16-row row-groups. K/V B-fragments are loaded once per
// ks and feed both row-groups' mma -> 1.5 LDS/mma (was 2.5). Per-row
// arithmetic identical to v1/v2 (same mma order, same softmax order).
// ---------------------------------------------------------------------------
#define QLD 68
#define VLD 72
// Q:128x68, P:128x68, K:64x68, V:64x72 floats = 105472 bytes
#define ATT_SMEM ((128 * QLD + 128 * QLD + 64 * QLD + 64 * VLD) * 4)

__global__ __launch_bounds__(128, 2)
void attn_tf32(const float* __restrict__ qkv, float* __restrict__ out)
{
    extern __shared__ unsigned sm[];
    unsigned* q_sm = sm;                       // 128 x QLD
    unsigned* p_sm = sm + 128 * QLD;           // 128 x QLD
    unsigned* k_sm = sm + 2 * 128 * QLD;       // 64 x QLD
    unsigned* v_sm = sm + 2 * 128 * QLD + 64 * QLD;   // 64 x VLD

    const int tid  = threadIdx.x;
    const int warp = tid >> 5;
    const int lane = tid & 31;
    const int g    = lane >> 2;
    const int tig  = lane & 3;
    const int wr   = warp * 32;               // warp owns rows [wr, wr+32)
    const int bh = blockIdx.y;
    const int b = bh >> 4;
    const int h = bh & 15;
    const int q0 = blockIdx.x * 128;
    const size_t tok0 = (size_t)b * SS;

    // Load Q tile (128 x 64): 2048 float4 / 128 threads = 16 iters
    #pragma unroll
    for (int it = 0; it < 16; ++it) {
        int i = tid + it * 128;
        int r = i >> 4, c = (i & 15) * 4;
        float4 v4 = *(const float4*)&qkv[(tok0 + q0 + r) * H3 + h * HD + c];
        q_sm[r * QLD + c + 0] = f2tf(v4.x);
        q_sm[r * QLD + c + 1] = f2tf(v4.y);
        q_sm[r * QLD + c + 2] = f2tf(v4.z);
        q_sm[r * QLD + c + 3] = f2tf(v4.w);
    }

    // Online-softmax state for 2 row-groups (rows wr+16*rg+g, +8)
    float m[2][2], l[2][2];
    float o[2][8][4];
    #pragma unroll
    for (int rg = 0; rg < 2; ++rg) {
        m[rg][0] = -1e30f; m[rg][1] = -1e30f;
        l[rg][0] = 0.f;    l[rg][1] = 0.f;
        #pragma unroll
        for (int j = 0; j < 8; ++j)
            #pragma unroll
            for (int e = 0; e < 4; ++e) o[rg][j][e] = 0.f;
    }
    __syncthreads();

    const int ntiles = 2 * blockIdx.x + 2;   // causal: k0c <= q0 + 127
    for (int t = 0; t < ntiles; ++t) {
        const int k0c = t * 64;
        // Load K and V tiles (64 x 64 each): 1024 float4 / 128 thr = 8 iters
        #pragma unroll
        for (int it = 0; it < 8; ++it) {
            int i = tid + it * 128;
            int r = i >> 4, c = (i & 15) * 4;
            size_t base = (tok0 + k0c + r) * H3 + h * HD + c;
            float4 kv = *(const float4*)&qkv[base + HH];
            float4 vv = *(const float4*)&qkv[base + 2 * HH];
            k_sm[r * QLD + c + 0] = f2tf(kv.x);
            k_sm[r * QLD + c + 1] = f2tf(kv.y);
            k_sm[r * QLD + c + 2] = f2tf(kv.z);
            k_sm[r * QLD + c + 3] = f2tf(kv.w);
            v_sm[r * VLD + c + 0] = f2tf(vv.x);
            v_sm[r * VLD + c + 1] = f2tf(vv.y);
            v_sm[r * VLD + c + 2] = f2tf(vv.z);
            v_sm[r * VLD + c + 3] = f2tf(vv.w);
        }
        __syncthreads();

        // S = Q @ K^T for both row-groups; B fragments shared across rgs
        float s[2][8][4];
        #pragma unroll
        for (int rg = 0; rg < 2; ++rg)
            #pragma unroll
            for (int j = 0; j < 8; ++j)
                #pragma unroll
                for (int e = 0; e < 4; ++e) s[rg][j][e] = 0.f;

        #pragma unroll
        for (int ks = 0; ks < 8; ++ks) {
            unsigned a[2][4];
            #pragma unroll
            for (int rg = 0; rg < 2; ++rg) {
                int rbase = wr + 16 * rg;
                a[rg][0] = q_sm[(rbase + g    ) * QLD + 8 * ks + tig];
                a[rg][1] = q_sm[(rbase + g + 8) * QLD + 8 * ks + tig];
                a[rg][2] = q_sm[(rbase + g    ) * QLD + 8 * ks + tig + 4];
                a[rg][3] = q_sm[(rbase + g + 8) * QLD + 8 * ks + tig + 4];
            }
            #pragma unroll
            for (int j = 0; j < 8; ++j) {
                unsigned b0 = k_sm[(8 * j + g) * QLD + 8 * ks + tig];
                unsigned b1 = k_sm[(8 * j + g) * QLD + 8 * ks + tig + 4];
                mma_tf32(s[0][j], a[0][0], a[0][1], a[0][2], a[0][3], b0, b1);
                mma_tf32(s[1][j], a[1][0], a[1][1], a[1][2], a[1][3], b0, b1);
            }
        }

        // Causal mask (apply when the tile reaches past this warp's first row)
        if (k0c + 63 > q0 + wr) {
            #pragma unroll
            for (int rg = 0; rg < 2; ++rg) {
                int rg0 = q0 + wr + 16 * rg + g;
                int rg1 = rg0 + 8;
                #pragma unroll
                for (int j = 0; j < 8; ++j) {
                    int cg = k0c + 8 * j + 2 * tig;
                    if (cg     > rg0) s[rg][j][0] = -1e30f;
                    if (cg + 1 > rg0) s[rg][j][1] = -1e30f;
                    if (cg     > rg1) s[rg][j][2] = -1e30f;
                    if (cg + 1 > rg1) s[rg][j][3] = -1e30f;
                }
            }
        }

        // Online softmax per row-group (identical per-row sequence to v1/v2)
        #pragma unroll
        for (int rg = 0; rg < 2; ++rg) {
            float rmax0 = -1e30f, rmax1 = -1e30f;
            #pragma unroll
            for (int j = 0; j < 8; ++j) {
                rmax0 = fmaxf(rmax0, fmaxf(s[rg][j][0], s[rg][j][1]));
                rmax1 = fmaxf(rmax1, fmaxf(s[rg][j][2], s[rg][j][3]));
            }
            rmax0 = fmaxf(rmax0, __shfl_xor_sync(0xffffffffu, rmax0, 1));
            rmax0 = fmaxf(rmax0, __shfl_xor_sync(0xffffffffu, rmax0, 2));
            rmax1 = fmaxf(rmax1, __shfl_xor_sync(0xffffffffu, rmax1, 1));
            rmax1 = fmaxf(rmax1, __shfl_xor_sync(0xffffffffu, rmax1, 2));

            float mn0 = fmaxf(m[rg][0], rmax0);
            float mn1 = fmaxf(m[rg][1], rmax1);
            float sum0 = 0.f, sum1 = 0.f;
            #pragma unroll
            for (int j = 0; j < 8; ++j) {
                s[rg][j][0] = __expf(s[rg][j][0] - mn0); sum0 += s[rg][j][0];
                s[rg][j][1] = __expf(s[rg][j][1] - mn0); sum0 += s[rg][j][1];
                s[rg][j][2] = __expf(s[rg][j][2] - mn1); sum1 += s[rg][j][2];
                s[rg][j][3] = __expf(s[rg][j][3] - mn1); sum1 += s[rg][j][3];
            }
            sum0 += __shfl_xor_sync(0xffffffffu, sum0, 1);
            sum0 += __shfl_xor_sync(0xffffffffu, sum0, 2);
            sum1 += __shfl_xor_sync(0xffffffffu, sum1, 1);
            sum1 += __shfl_xor_sync(0xffffffffu, sum1, 2);

            float al0 = __expf(m[rg][0] - mn0);
            float al1 = __expf(m[rg][1] - mn1);
            l[rg][0] = l[rg][0] * al0 + sum0;
            l[rg][1] = l[rg][1] * al1 + sum1;
            m[rg][0] = mn0; m[rg][1] = mn1;

            int rbase = wr + 16 * rg;
            #pragma unroll
            for (int j = 0; j < 8; ++j) {
                o[rg][j][0] *= al0; o[rg][j][1] *= al0;
                o[rg][j][2] *= al1; o[rg][j][3] *= al1;
                p_sm[(rbase + g    ) * QLD + 8 * j + 2 * tig    ] = f2tf(s[rg][j][0]);
                p_sm[(rbase + g    ) * QLD + 8 * j + 2 * tig + 1] = f2tf(s[rg][j][1]);
                p_sm[(rbase + g + 8) * QLD + 8 * j + 2 * tig    ] = f2tf(s[rg][j][2]);
                p_sm[(rbase + g + 8) * QLD + 8 * j + 2 * tig + 1] = f2tf(s[rg][j][3]);
            }
        }
        __syncwarp();

        // O += P @ V  (V B-fragments shared across row-groups)
        #pragma unroll
        for (int ks = 0; ks < 8; ++ks) {
            unsigned a[2][4];
            #pragma unroll
            for (int rg = 0; rg < 2; ++rg) {
                int rbase = wr + 16 * rg;
                a[rg][0] = p_sm[(rbase + g    ) * QLD + 8 * ks + tig];
                a[rg][1] = p_sm[(rbase + g + 8) * QLD + 8 * ks + tig];
                a[rg][2] = p_sm[(rbase + g    ) * QLD + 8 * ks + tig + 4];
                a[rg][3] = p_sm[(rbase + g + 8) * QLD + 8 * ks + tig + 4];
            }
            #pragma unroll
            for (int j = 0; j < 8; ++j) {
                unsigned b0 = v_sm[(8 * ks + tig    ) * VLD + 8 * j + g];
                unsigned b1 = v_sm[(8 * ks + tig + 4) * VLD + 8 * j + g];
                mma_tf32(o[0][j], a[0][0], a[0][1], a[0][2], a[0][3], b0, b1);
                mma_tf32(o[1][j], a[1][0], a[1][1], a[1][2], a[1][3], b0, b1);
            }
        }
        __syncthreads();
    }

    // Normalize, tf32-round, write out (feeds proj GEMM as pre-rounded A)
    #pragma unroll
    for (int rg = 0; rg < 2; ++rg) {
        float i0 = 1.f / l[rg][0], i1 = 1.f / l[rg][1];
        int rbase = wr + 16 * rg;
        #pragma unroll
        for (int j = 0; j < 8; ++j) {
            int gn = h * HD + 8 * j + 2 * tig;
            float2 r0 = make_float2(__uint_as_float(f2tf(o[rg][j][0] * i0)),
                                    __uint_as_float(f2tf(o[rg][j][1] * i0)));
            float2 r1 = make_float2(__uint_as_float(f2tf(o[rg][j][2] * i1)),
                                    __uint_as_float(f2tf(o[rg][j][3] * i1)));
            *(float2*)&out[(tok0 + q0 + rbase + g    ) * HH + gn] = r0;
            *(float2*)&out[(tok0 + q0 + rbase + g + 8) * HH + gn] = r1;
        }
    }
}

// ---------------------------------------------------------------------------
extern "C" void kernel_launch(void* const* d_in, const int* in_sizes, int n_in,
                              void* d_out, int out_size)
{
    const float* hidden = (const float*)d_in[0];
    const float* W_attn = (const float*)d_in[1];
    const float* b_attn = (const float*)d_in[2];
    const float* W_proj = (const float*)d_in[3];
    const float* b_proj = (const float*)d_in[4];
    const float* q_gamma = (const float*)d_in[5];
    const float* q_beta  = (const float*)d_in[6];
    const float* k_gamma = (const float*)d_in[7];
    const float* k_beta  = (const float*)d_in[8];
    float* out = (float*)d_out;

    float* qkv; cudaGetSymbolAddress((void**)&qkv, g_qkv);
    float* att; cudaGetSymbolAddress((void**)&att, g_att);
    float* hid; cudaGetSymbolAddress((void**)&hid, g_hid);
    float* wa;  cudaGetSymbolAddress((void**)&wa,  g_wa);
    float* wp;  cudaGetSymbolAddress((void**)&wp,  g_wp);

    static bool attr_set = false;
    if (!attr_set) {
        cudaFuncSetAttribute(attn_tf32,
                             cudaFuncAttributeMaxDynamicSharedMemorySize, ATT_SMEM);
        attr_set = true;
    }

    // 0) Pre-round GEMM inputs to tf32 (rna) once
    round_tf32_kernel<<<(NTOK * HH) / 1024, 256>>>(hidden, hid);
    round_tf32_kernel<<<(HH * H3) / 1024, 256>>>(W_attn, wa);
    round_tf32_kernel<<<(HH * HH) / 1024, 256>>>(W_proj, wp);

    // 1) QKV GEMM: [4096,1024] @ [1024,3072] + bias
    gemm_tf32<<<dim3(H3 / 128, NTOK / 128), 256>>>(
        hid, wa, b_attn, qkv, NTOK, H3, HH);

    // 2) QK LayerNorm in place (softmax scale folded into q)
    qk_ln_kernel<<<(2 * NTOK * NHEAD) / 8, 256>>>(
        qkv, q_gamma, q_beta, k_gamma, k_beta);

    // 3) Causal attention v3 (Br=128, 4 warps x 32 rows, shared B fragments)
    attn_tf32<<<dim3(SS / 128, BB * NHEAD), 128, ATT_SMEM>>>(qkv, att);

    // 4) Output projection: [4096,1024] @ [1024,1024] + bias
    gemm_tf32<<<dim3(HH / 128, NTOK / 128), 256>>>(
        att, wp, b_proj, out, NTOK, HH, HH);
}